// round 3
// baseline (speedup 1.0000x reference)
#include <cuda_runtime.h>
#include <cstdint>
#include <math.h>

// Problem constants
#define BB 64
#define TT 512
#define DD 512
#define HH 1024
#define G4 4096   // 4*H
#define NBLK 128

// ---------------- device scratch (no cudaMalloc allowed) ----------------
__device__ float g_xg[(size_t)BB * TT * G4];   // input projection + biases (512 MB)
__device__ float g_h[2][BB * HH];              // double-buffered hidden state
__device__ float g_c[BB * HH];                 // cell state (CTA-exclusive columns)
__device__ unsigned g_bar;                     // grid barrier counter (monotonic per run)

// ---------------- f32x2 packed-FMA helpers (sm_103a FFMA2) ----------------
__device__ __forceinline__ void fma2(unsigned long long& d,
                                     unsigned long long a, unsigned long long b) {
    asm("fma.rn.f32x2 %0, %1, %2, %0;" : "+l"(d) : "l"(a), "l"(b));
}
__device__ __forceinline__ unsigned long long bcast2(float x) {
    unsigned long long r;
    asm("mov.b64 %0, {%1, %1};" : "=l"(r) : "f"(x));
    return r;
}
__device__ __forceinline__ float2 unpack2(unsigned long long d) {
    float2 v;
    asm("mov.b64 {%0, %1}, %2;" : "=f"(v.x), "=f"(v.y) : "l"(d));
    return v;
}

// ---------------- init ----------------
__global__ void init_state(const float* __restrict__ h0, const float* __restrict__ c0) {
    int idx = blockIdx.x * blockDim.x + threadIdx.x;
    if (idx == 0) g_bar = 0u;
    if (idx < BB * HH) {
        int k = idx & (HH - 1);
        g_h[0][idx] = h0[k];
        g_c[idx]    = c0[k];
    }
}

// ---------------- xg GEMM with FFMA2 inner loop ----------------
#define BM 128
#define BN 128
#define BK 16
__global__ __launch_bounds__(256, 2)
void xg_gemm(const float* __restrict__ X, const float* __restrict__ Wih,
             const float* __restrict__ bih, const float* __restrict__ bhh) {
    __shared__ float As[BK][BM + 4];
    __shared__ float Bs[BK][BN + 4];

    int tid = threadIdx.x;
    int bm = blockIdx.y;
    int bn = blockIdx.x;

    int trow = (tid / 16) * 8;
    int tcol = (tid % 16) * 8;

    const float* Aofs = X   + (size_t)bm * BM * DD;
    const float* Bofs = Wih + (size_t)bn * BN * DD;

    int a_r = tid >> 2;
    int a_c = (tid & 3) * 4;

    // acc[i][p] = packed pair (col 2p, col 2p+1) for row i
    unsigned long long acc[8][4];
#pragma unroll
    for (int i = 0; i < 8; i++)
#pragma unroll
        for (int p = 0; p < 4; p++) acc[i][p] = 0ull;

    for (int k0 = 0; k0 < DD; k0 += BK) {
#pragma unroll
        for (int i = 0; i < 2; i++) {
            float4 v = *(const float4*)(Aofs + (size_t)(a_r + i * 64) * DD + k0 + a_c);
            As[a_c + 0][a_r + i * 64] = v.x;
            As[a_c + 1][a_r + i * 64] = v.y;
            As[a_c + 2][a_r + i * 64] = v.z;
            As[a_c + 3][a_r + i * 64] = v.w;
        }
#pragma unroll
        for (int i = 0; i < 2; i++) {
            float4 v = *(const float4*)(Bofs + (size_t)(a_r + i * 64) * DD + k0 + a_c);
            Bs[a_c + 0][a_r + i * 64] = v.x;
            Bs[a_c + 1][a_r + i * 64] = v.y;
            Bs[a_c + 2][a_r + i * 64] = v.z;
            Bs[a_c + 3][a_r + i * 64] = v.w;
        }
        __syncthreads();
#pragma unroll
        for (int kk = 0; kk < BK; kk++) {
            // b pairs straight out of SMEM as b64 (16B-aligned)
            ulonglong2 b0 = *(const ulonglong2*)(&Bs[kk][tcol]);
            ulonglong2 b1 = *(const ulonglong2*)(&Bs[kk][tcol + 4]);
            float4 a0 = *(const float4*)(&As[kk][trow]);
            float4 a1 = *(const float4*)(&As[kk][trow + 4]);
            float av[8] = {a0.x, a0.y, a0.z, a0.w, a1.x, a1.y, a1.z, a1.w};
#pragma unroll
            for (int i = 0; i < 8; i++) {
                unsigned long long ab = bcast2(av[i]);
                fma2(acc[i][0], ab, b0.x);
                fma2(acc[i][1], ab, b0.y);
                fma2(acc[i][2], ab, b1.x);
                fma2(acc[i][3], ab, b1.y);
            }
        }
        __syncthreads();
    }

    float bias[8];
#pragma unroll
    for (int j = 0; j < 8; j++) {
        int g = bn * BN + tcol + j;
        bias[j] = bih[g] + bhh[g];
    }
#pragma unroll
    for (int i = 0; i < 8; i++) {
        size_t row = (size_t)(bm * BM + trow + i);
        float* op = g_xg + row * G4 + bn * BN + tcol;
#pragma unroll
        for (int p2 = 0; p2 < 2; p2++) {
            float2 u0 = unpack2(acc[i][p2 * 2 + 0]);
            float2 u1 = unpack2(acc[i][p2 * 2 + 1]);
            float4 v;
            v.x = u0.x + bias[p2 * 4 + 0];
            v.y = u0.y + bias[p2 * 4 + 1];
            v.z = u1.x + bias[p2 * 4 + 2];
            v.w = u1.y + bias[p2 * 4 + 3];
            *(float4*)(op + p2 * 4) = v;
        }
    }
}

// ---------------- persistent LSTM recurrence ----------------
#define KC 128
#define WS_STRIDE 36
#define HROW 132
#define SMEM_FLOATS (36864 + 16896 + 2112)
#define SMEM_BYTES  (SMEM_FLOATS * 4)

__device__ __forceinline__ float sigm(float x) { return 1.f / (1.f + expf(-x)); }

__device__ __forceinline__ void cp16(void* sdst, const void* gsrc) {
    unsigned d = (unsigned)__cvta_generic_to_shared(sdst);
    asm volatile("cp.async.cg.shared.global [%0], [%1], 16;\n" :: "r"(d), "l"(gsrc));
}
__device__ __forceinline__ void cp_commit() {
    asm volatile("cp.async.commit_group;\n" ::: "memory");
}
__device__ __forceinline__ void cp_wait1() {
    asm volatile("cp.async.wait_group 1;\n" ::: "memory");
}
__device__ __forceinline__ void cp_wait0() {
    asm volatile("cp.async.wait_group 0;\n" ::: "memory");
}

__global__ __launch_bounds__(256, 1)
void lstm_persistent(const float* __restrict__ Whh, const int* __restrict__ mask,
                     float* __restrict__ out) {
    extern __shared__ float sm[];
    float* Ws  = sm;                       // [1024][36]
    float* hs  = sm + 1024 * WS_STRIDE;    // [2][64][HROW]
    float* gsm = hs + 2 * 64 * HROW;       // per-warp [8][33] gate stash

    __shared__ int act[BB], inact[BB], counts[2], msh[BB];

    int tid  = threadIdx.x;
    int base = blockIdx.x * 8;
    int w    = tid >> 5, lane = tid & 31;
    int q    = lane >> 3, c = lane & 7;
    int r0   = w * 8 + q * 2;

    // ---- load W slice once: Ws[k][col], col = gate*8 + u ----
    for (int i = tid; i < 32 * 256; i += 256) {
        int col = i >> 8;
        int k4  = (i & 255) * 4;
        int gate = col >> 3, u = col & 7;
        const float* wp = Whh + ((size_t)(gate * HH + base + u)) * HH + k4;
        float4 v = *(const float4*)wp;
        Ws[(k4 + 0) * WS_STRIDE + col] = v.x;
        Ws[(k4 + 1) * WS_STRIDE + col] = v.y;
        Ws[(k4 + 2) * WS_STRIDE + col] = v.z;
        Ws[(k4 + 3) * WS_STRIDE + col] = v.w;
    }
    __syncthreads();

    for (int t = 0; t < TT; t++) {
        const float* hcur  = g_h[t & 1];
        float*       hnext = g_h[(t + 1) & 1];

        if (tid < BB) msh[tid] = mask[tid * TT + t];
        __syncthreads();
        if (tid == 0) {
            int na = 0, ni = 0;
            for (int b = 0; b < BB; b++) {
                if (msh[b]) act[na++] = b; else inact[ni++] = b;
            }
            counts[0] = na; counts[1] = ni;
        }
        __syncthreads();
        int nact = counts[0], ninact = counts[1];

        for (int i = tid; i < ninact * 8; i += 256) {
            int r = i >> 3, u = i & 7;
            int b = inact[r];
            int idx = b * HH + base + u;
            float v = __ldcg(hcur + idx);
            hnext[idx] = v;
            out[((size_t)b * TT + t) * HH + base + u] = v;
        }

        // packed accumulators: accI J-pair layout (row i, cols 2p/2p+1)
        unsigned long long acc00 = 0ull, acc01 = 0ull, acc10 = 0ull, acc11 = 0ull;
        bool wact = (w * 8 < nact);

        for (int i = tid; i < nact * 32; i += 256) {
            int r = i >> 5, ks = i & 31;
            cp16(hs + (size_t)r * HROW + ks * 4,
                 hcur + (size_t)act[r] * HH + ks * 4);
        }
        cp_commit();

        for (int ch = 0; ch < 8; ch++) {
            int nxt = ch + 1;
            if (nxt < 8) {
                float* dstb = hs + (size_t)(nxt & 1) * 64 * HROW;
                const float* srcb = hcur + nxt * KC;
                for (int i = tid; i < nact * 32; i += 256) {
                    int r = i >> 5, ks = i & 31;
                    cp16(dstb + (size_t)r * HROW + ks * 4,
                         srcb + (size_t)act[r] * HH + ks * 4);
                }
                cp_commit();
                cp_wait1();
            } else {
                cp_commit();
                cp_wait0();
            }
            __syncthreads();

            if (wact) {
                const float* wp = Ws + (size_t)(ch * KC) * WS_STRIDE + c * 4;
                const float* hp = hs + (size_t)(ch & 1) * 64 * HROW + (size_t)r0 * HROW;
#pragma unroll 4
                for (int kk = 0; kk < KC; kk += 2) {
                    ulonglong2 w0 = *(const ulonglong2*)(wp + (size_t)kk * WS_STRIDE);
                    ulonglong2 w1 = *(const ulonglong2*)(wp + (size_t)(kk + 1) * WS_STRIDE);
                    float2 ha = *(const float2*)(hp + kk);
                    float2 hb = *(const float2*)(hp + HROW + kk);
                    unsigned long long hax = bcast2(ha.x), hbx = bcast2(hb.x);
                    fma2(acc00, hax, w0.x); fma2(acc01, hax, w0.y);
                    fma2(acc10, hbx, w0.x); fma2(acc11, hbx, w0.y);
                    unsigned long long hay = bcast2(ha.y), hby = bcast2(hb.y);
                    fma2(acc00, hay, w1.x); fma2(acc01, hay, w1.y);
                    fma2(acc10, hby, w1.x); fma2(acc11, hby, w1.y);
                }
            }
            __syncthreads();
        }

        // ---- epilogue ----
        float accf[2][4];
        {
            float2 u;
            u = unpack2(acc00); accf[0][0] = u.x; accf[0][1] = u.y;
            u = unpack2(acc01); accf[0][2] = u.x; accf[0][3] = u.y;
            u = unpack2(acc10); accf[1][0] = u.x; accf[1][1] = u.y;
            u = unpack2(acc11); accf[1][2] = u.x; accf[1][3] = u.y;
        }
        float* gw = gsm + w * (8 * 33);
        if (wact) {
            int gate = c >> 1;
            int gg0  = gate * HH + base + (c & 1) * 4;
#pragma unroll
            for (int i = 0; i < 2; i++) {
                int r = r0 + i;
                if (r < nact) {
                    int b = act[r];
                    float4 xv = *(const float4*)(g_xg + ((size_t)b * TT + t) * G4 + gg0);
                    int rl = q * 2 + i;
                    gw[rl * 33 + c * 4 + 0] = accf[i][0] + xv.x;
                    gw[rl * 33 + c * 4 + 1] = accf[i][1] + xv.y;
                    gw[rl * 33 + c * 4 + 2] = accf[i][2] + xv.z;
                    gw[rl * 33 + c * 4 + 3] = accf[i][3] + xv.w;
                }
            }
        }
        __syncwarp();
        if (wact) {
#pragma unroll
            for (int ee = 0; ee < 2; ee++) {
                int e = lane * 2 + ee;
                int rl = e >> 3, u = e & 7;
                int r = w * 8 + rl;
                if (r < nact) {
                    int b = act[r];
                    float gi = gw[rl * 33 + u];
                    float gf = gw[rl * 33 + 8 + u];
                    float gG = gw[rl * 33 + 16 + u];
                    float go = gw[rl * 33 + 24 + u];
                    float iv = sigm(gi);
                    float fv = sigm(gf);
                    float gv = tanhf(gG);
                    float ov = sigm(go);
                    int idx = b * HH + base + u;
                    float cn = fv * g_c[idx] + iv * gv;
                    float hn = ov * tanhf(cn);
                    g_c[idx] = cn;
                    hnext[idx] = hn;
                    out[((size_t)b * TT + t) * HH + base + u] = hn;
                }
            }
        }

        // ---- grid barrier ----
        __syncthreads();
        if (tid == 0) {
            __threadfence();
            atomicAdd(&g_bar, 1u);
            unsigned want = (unsigned)(t + 1) * NBLK;
            while (*(volatile unsigned*)&g_bar < want) { __nanosleep(64); }
        }
        __syncthreads();
        __threadfence();
    }
}

// ---------------- launch ----------------
extern "C" void kernel_launch(void* const* d_in, const int* in_sizes, int n_in,
                              void* d_out, int out_size) {
    const float* x    = (const float*)d_in[0];
    const int*   mask = (const int*)  d_in[1];
    const float* Wih  = (const float*)d_in[2];
    const float* Whh  = (const float*)d_in[3];
    const float* bih  = (const float*)d_in[4];
    const float* bhh  = (const float*)d_in[5];
    const float* h0   = (const float*)d_in[6];
    const float* c0   = (const float*)d_in[7];
    float* out = (float*)d_out;

    cudaFuncSetAttribute(lstm_persistent, cudaFuncAttributeMaxDynamicSharedMemorySize, SMEM_BYTES);

    init_state<<<(BB * HH + 255) / 256, 256>>>(h0, c0);
    xg_gemm<<<dim3(G4 / BN, (BB * TT) / BM), 256>>>(x, Wih, bih, bhh);
    lstm_persistent<<<NBLK, 256, SMEM_BYTES>>>(Whh, mask, out);
}